// round 15
// baseline (speedup 1.0000x reference)
#include <cuda_runtime.h>
#include <cstddef>

#define BB  256
#define NS0 4096
#define NS1 2048
#define NS2 1024
#define NS3 512
#define E0  32768
#define E1  16384
#define E2  8192
#define DD  64

// ---- deg array layout: edge degs then cluster degs ----
#define EDEG0 0
#define EDEG1 (NS0)
#define EDEG2 (NS0 + NS1)
#define CDEG0 (NS0 + NS1 + NS2)
#define CDEG1 (CDEG0 + NS1)
#define CDEG2 (CDEG1 + NS2)
#define DEG_TOT (CDEG2 + NS3)

// ---- rp array layout ----
#define RP0 0
#define RP1 (NS0 + 1)
#define RP2 (NS0 + NS1 + 2)
#define CRP0 (NS0 + NS1 + NS2 + 3)
#define CRP1 (CRP0 + NS1 + 1)
#define CRP2 (CRP1 + NS2 + 1)
#define RP_TOT (CRP2 + NS3 + 1)

// ---- col array layout ----
#define COL0 0
#define COL1 (E0)
#define COL2 (E0 + E1)
#define CCOL0 (E0 + E1 + E2)
#define CCOL1 (CCOL0 + NS0)
#define CCOL2 (CCOL1 + NS1)
#define COL_TOT (CCOL2 + NS2)

// pool ping-pong: region A at 0 (max NS1 clusters), region B after it
#define POOLB_OFF ((size_t)NS1 * DD * BB)

// ---------------- scratch (device globals; no allocation) ----------------
__device__ float g_pool[(size_t)(NS1 + NS2) * DD * BB];  // 201 MB, [c][f][g] fp32
__device__ float g_x[(size_t)NS0 * 3 * BB];              // layer-0 x, [li][k][g]
__device__ float g_als[NS0 * BB];                        // [li][g]
__device__ float g_ald[NS0 * BB];
__device__ float g_ew[(size_t)E1 * BB];                  // normalized edge alphas (layers 1,2)
__device__ float g_sfa[NS1 * BB];                        // self alpha = 1/z
__device__ int   g_deg[DEG_TOT];
__device__ int   g_rp[RP_TOT];
__device__ int   g_wp[RP_TOT];
__device__ int   g_col[COL_TOT];
__device__ float g_partS[64 * 4];
__device__ float g_partSS[64 * 4];
__device__ float g_mean[DD];
__device__ float g_rstd[DD];
__device__ float g_qas[DD];
__device__ float g_qad[DD];
__device__ float g_cas;
__device__ float g_cad;
__device__ float g_weff[DD * DD];      // rstd-folded weights (layers 1,2)
__device__ float g_beff[DD];           // mean/rstd-folded bias

__device__ __forceinline__ float lrelu(float x) { return x > 0.f ? x : 0.2f * x; }

// ---------------- CSR build (edges AND cluster membership) ----------------
__global__ void zero_deg_kernel() {
    int i = blockIdx.x * blockDim.x + threadIdx.x;
    if (i < DEG_TOT) g_deg[i] = 0;
}

__global__ void count_all_kernel(const int* __restrict__ e0d, const int* __restrict__ e1d,
                                 const int* __restrict__ e2d, const int* __restrict__ c0d,
                                 const int* __restrict__ c1d, const int* __restrict__ c2d) {
    int b = blockIdx.x;
    int tid = threadIdx.x;
    if (b < 224) {
        const int* e; int epb, off, j0;
        if (b < 128)      { e = e0d; epb = E0; off = EDEG0; j0 = b * 256; }
        else if (b < 192) { e = e1d; epb = E1; off = EDEG1; j0 = (b - 128) * 256; }
        else              { e = e2d; epb = E2; off = EDEG2; j0 = (b - 192) * 256; }
        int j = j0 + tid;
        if (j < epb) atomicAdd(&g_deg[off + e[epb + j]], 1);
    } else {
        const int* c; int n, off, j0;
        if (b < 240)      { c = c0d; n = NS0; off = CDEG0; j0 = (b - 224) * 256; }
        else if (b < 248) { c = c1d; n = NS1; off = CDEG1; j0 = (b - 240) * 256; }
        else              { c = c2d; n = NS2; off = CDEG2; j0 = (b - 248) * 256; }
        int j = j0 + tid;
        if (j < n) atomicAdd(&g_deg[off + c[j]], 1);
    }
}

__global__ void scan_all_kernel() {
    const int degOffT[6] = {EDEG0, EDEG1, EDEG2, CDEG0, CDEG1, CDEG2};
    const int rpOffT[6]  = {RP0, RP1, RP2, CRP0, CRP1, CRP2};
    const int nT[6]      = {NS0, NS1, NS2, NS1, NS2, NS3};
    int degOff = degOffT[blockIdx.x], rpOff = rpOffT[blockIdx.x], n = nT[blockIdx.x];

    __shared__ int tsum[1024];
    int t = threadIdx.x;
    int chunk = (n + 1023) >> 10;
    int start = t * chunk;
    int s = 0;
    for (int i = 0; i < chunk; i++) {
        int idx = start + i;
        if (idx < n) s += g_deg[degOff + idx];
    }
    tsum[t] = s;
    __syncthreads();
    for (int off = 1; off < 1024; off <<= 1) {
        int v = (t >= off) ? tsum[t - off] : 0;
        __syncthreads();
        tsum[t] += v;
        __syncthreads();
    }
    int run = (t == 0) ? 0 : tsum[t - 1];
    for (int i = 0; i < chunk; i++) {
        int idx = start + i;
        if (idx < n) {
            g_rp[rpOff + idx] = run;
            g_wp[rpOff + idx] = run;
            run += g_deg[degOff + idx];
        }
    }
    if (t == 1023) g_rp[rpOff + n] = tsum[1023];
}

__global__ void scatter_all_kernel(const int* __restrict__ e0d, const int* __restrict__ e1d,
                                   const int* __restrict__ e2d, const int* __restrict__ c0d,
                                   const int* __restrict__ c1d, const int* __restrict__ c2d) {
    int b = blockIdx.x;
    int tid = threadIdx.x;
    if (b < 224) {
        const int* e; int epb, rpOff, colOff, j0;
        if (b < 128)      { e = e0d; epb = E0; rpOff = RP0; colOff = COL0; j0 = b * 256; }
        else if (b < 192) { e = e1d; epb = E1; rpOff = RP1; colOff = COL1; j0 = (b - 128) * 256; }
        else              { e = e2d; epb = E2; rpOff = RP2; colOff = COL2; j0 = (b - 192) * 256; }
        int j = j0 + tid;
        if (j < epb) {
            int s = e[j];
            int d = e[epb + j];
            int p = atomicAdd(&g_wp[rpOff + d], 1);
            g_col[colOff + p] = s;
        }
    } else {
        const int* c; int n, rpOff, colOff, j0;
        if (b < 240)      { c = c0d; n = NS0; rpOff = CRP0; colOff = CCOL0; j0 = (b - 224) * 256; }
        else if (b < 248) { c = c1d; n = NS1; rpOff = CRP1; colOff = CCOL1; j0 = (b - 240) * 256; }
        else              { c = c2d; n = NS2; rpOff = CRP2; colOff = CCOL2; j0 = (b - 248) * 256; }
        int j = j0 + tid;
        if (j < n) {
            int p = atomicAdd(&g_wp[rpOff + c[j]], 1);
            g_col[colOff + p] = j;
        }
    }
}

// ---------------- layer-0 prep: qas = W@a (no BN) ----------------
__global__ void prep0_kernel(const float* __restrict__ Wg,
                             const float* __restrict__ as_, const float* __restrict__ ad_) {
    int t = threadIdx.x;   // 64
    if (t < 3) {
        float ps = 0.f, pd = 0.f;
        for (int f = 0; f < 64; f++) {
            float w = Wg[t * 64 + f];
            ps = fmaf(w, as_[f], ps);
            pd = fmaf(w, ad_[f], pd);
        }
        g_qas[t] = ps;
        g_qad[t] = pd;
    }
    if (t == 0) { g_cas = 0.f; g_cad = 0.f; }
}

// ---------------- layers 1,2: BN finalize + fold into W', b', qas, cas ----------------
__global__ void bn_prep_kernel(const float* __restrict__ Wg, const float* __restrict__ as_,
                               const float* __restrict__ ad_, const float* __restrict__ bias,
                               int nrows) {
    __shared__ float smean[64], srstd[64], sc[64], sd[64];
    int t = threadIdx.x;
    if (t < 64) {
        double S  = (double)g_partS[t * 4] + g_partS[t * 4 + 1] + g_partS[t * 4 + 2] + g_partS[t * 4 + 3];
        double SS = (double)g_partSS[t * 4] + g_partSS[t * 4 + 1] + g_partSS[t * 4 + 2] + g_partSS[t * 4 + 3];
        double mu  = S / nrows;
        double var = SS / nrows - mu * mu;
        float m = (float)mu;
        float r = (float)rsqrt(var + 1e-5);
        smean[t] = m; srstd[t] = r;
        g_mean[t] = m; g_rstd[t] = r;
    }
    __syncthreads();
    if (t < 64) {
        float ps = 0.f, pd = 0.f;
        for (int f = 0; f < 64; f++) {
            float w = Wg[t * 64 + f];
            ps = fmaf(w, as_[f], ps);
            pd = fmaf(w, ad_[f], pd);
        }
        ps *= srstd[t]; pd *= srstd[t];
        g_qas[t] = ps; g_qad[t] = pd;
        sc[t] = smean[t] * ps; sd[t] = smean[t] * pd;
    }
    for (int i = t; i < 4096; i += 256)
        g_weff[i] = srstd[i >> 6] * Wg[i];
    __syncthreads();
    if (t < 64) {
        float bb = bias[t];
        for (int k = 0; k < 64; k++)
            bb -= srstd[k] * smean[k] * Wg[k * 64 + t];
        g_beff[t] = bb;
    }
    if (t == 0) {
        float S = 0.f;
        for (int k = 0; k < 64; k++) S += sc[k];
        g_cas = S;
    }
    if (t == 1) {
        float D = 0.f;
        for (int k = 0; k < 64; k++) D += sd[k];
        g_cad = D;
    }
}

// ---------------- layer 0: transpose x to graph-innermost + attention logits ----------------
__global__ __launch_bounds__(256) void trans_att0_kernel(const float* __restrict__ xin) {
    __shared__ float sm[24 * 132];
    __shared__ float qs[3], qd[3];
    int t = threadIdx.x;
    int li0 = (blockIdx.x >> 1) * 8;
    int g0  = (blockIdx.x & 1) * 128;
    if (t < 3) { qs[t] = g_qas[t]; qd[t] = g_qad[t]; }

    for (int i = t; i < 3072; i += 256) {
        int g = i / 24;
        int rem = i - g * 24;           // li*3 + k
        sm[rem * 132 + g] = xin[((size_t)(g0 + g) * NS0 + li0 + rem / 3) * 3 + rem % 3];
    }
    __syncthreads();
    for (int i = t; i < 3072; i += 256) {
        int r = i >> 7;                  // 0..23
        int g = i & 127;
        g_x[((size_t)(li0 + r / 3) * 3 + r % 3) * 256 + g0 + g] = sm[r * 132 + g];
    }
    for (int i = t; i < 1024; i += 256) {
        int li = i >> 7;
        int g  = i & 127;
        const float* row = sm + li * 3 * 132 + g;
        float a = row[0] * qs[0] + row[132] * qs[1] + row[264] * qs[2];
        float d = row[0] * qd[0] + row[132] * qd[1] + row[264] * qd[2];
        g_als[(li0 + li) * 256 + g0 + g] = a;
        g_ald[(li0 + li) * 256 + g0 + g] = d;
    }
}

// ---------------- layer 0: fused x-space agg + GEMM(K=3) + bias + relu + max-pool ----------------
__global__ __launch_bounds__(256) void agg0_fused_kernel(const float* __restrict__ Wg,
                                                         const float* __restrict__ bias) {
    __shared__ float sw[192], sb[64];
    __shared__ float su[2 * 396];       // [m][k*132 + g]
    int t = threadIdx.x;
    int lc = blockIdx.x >> 1;
    int gb = blockIdx.x & 1;
    int m  = t >> 7;
    int g  = t & 127;
    int gg = gb * 128 + g;

    if (t < 192) sw[t] = Wg[t];
    else sb[t - 192] = bias[t - 192];

    int m0  = g_rp[CRP0 + lc];
    int cnt = g_rp[CRP0 + lc + 1] - m0;
    int li  = g_col[CCOL0 + m0 + (m < cnt ? m : 0)];

    float adi = g_ald[li * 256 + gg];
    float es  = lrelu(g_als[li * 256 + gg] + adi);
    float z = 1.f;
    float u0 = g_x[((size_t)li * 3 + 0) * 256 + gg];
    float u1 = g_x[((size_t)li * 3 + 1) * 256 + gg];
    float u2 = g_x[((size_t)li * 3 + 2) * 256 + gg];

    int r0 = g_rp[RP0 + li], r1 = g_rp[RP0 + li + 1];
#pragma unroll 4
    for (int j = r0; j < r1; j++) {
        int s = g_col[COL0 + j];
        float w = __expf(lrelu(g_als[s * 256 + gg] + adi) - es);
        z += w;
        u0 = fmaf(w, g_x[((size_t)s * 3 + 0) * 256 + gg], u0);
        u1 = fmaf(w, g_x[((size_t)s * 3 + 1) * 256 + gg], u1);
        u2 = fmaf(w, g_x[((size_t)s * 3 + 2) * 256 + gg], u2);
    }
    float iz = __fdividef(1.f, z);
    su[m * 396 + 0   + g] = u0 * iz;
    su[m * 396 + 132 + g] = u1 * iz;
    su[m * 396 + 264 + g] = u2 * iz;
    __syncthreads();

    int mh = t >> 7;
    float a0 = su[0   + g], a1 = su[132 + g], a2 = su[264 + g];
    float b0 = su[396 + g], b1 = su[528 + g], b2 = su[660 + g];
    size_t outBase = ((size_t)lc * 64 + mh * 32) * 256 + gb * 128 + g;
#pragma unroll 8
    for (int ff = 0; ff < 32; ff++) {
        int f = mh * 32 + ff;
        float w0 = sw[f], w1 = sw[64 + f], w2 = sw[128 + f];
        float oA = sb[f] + a0 * w0 + a1 * w1 + a2 * w2;
        float oB = sb[f] + b0 * w0 + b1 * w1 + b2 * w2;
        g_pool[outBase + (size_t)ff * 256] = fmaxf(fmaxf(oA, oB), 0.f);
    }
}

// ---------------- layers 1,2: attention logits from raw pool (BN folded into q) ----------------
__global__ __launch_bounds__(256) void att_kernel(size_t poolOff) {
    __shared__ float qs[64], qd[64];
    __shared__ float sredS[2048], sredD[2048];
    int t = threadIdx.x;
    int tc = t >> 5, tr = t & 31;
    int li = blockIdx.x;
    if (t < 64) { qs[t] = g_qas[t]; qd[t] = g_qad[t]; }
    __syncthreads();

    const float* row = g_pool + poolOff + (size_t)li * 64 * 256;
    float ps[8], pd[8];
#pragma unroll
    for (int i = 0; i < 8; i++) { ps[i] = 0.f; pd[i] = 0.f; }
#pragma unroll
    for (int j = 0; j < 8; j++) {
        int f = tc * 8 + j;
        float qv = qs[f], qw = qd[f];
#pragma unroll
        for (int i = 0; i < 8; i++) {
            float v = row[(size_t)f * 256 + tr + 32 * i];
            ps[i] = fmaf(v, qv, ps[i]);
            pd[i] = fmaf(v, qw, pd[i]);
        }
    }
#pragma unroll
    for (int i = 0; i < 8; i++) {
        sredS[(tc * 8 + i) * 32 + tr] = ps[i];
        sredD[(tc * 8 + i) * 32 + tr] = pd[i];
    }
    __syncthreads();
    {
        int i = t >> 5, r = t & 31;
        float S = 0.f, D = 0.f;
#pragma unroll
        for (int c = 0; c < 8; c++) {
            S += sredS[(c * 8 + i) * 32 + r];
            D += sredD[(c * 8 + i) * 32 + r];
        }
        g_als[li * 256 + r + 32 * i] = S - g_cas;
        g_ald[li * 256 + r + 32 * i] = D - g_cad;
    }
}

// ---------------- layers 1,2: precompute normalized edge alphas ----------------
// block = dst node li, threads = 256 graphs. Writes alpha to g_ew[edgePos][g],
// self alpha (1/z) to g_sfa[li][g]. Each (edge, graph) exp computed ONCE.
__global__ __launch_bounds__(256) void ew_kernel(int rpOff, int colOff) {
    int li = blockIdx.x;
    int g  = threadIdx.x;
    float adi = g_ald[li * 256 + g];
    float es  = lrelu(g_als[li * 256 + g] + adi);
    int r0 = g_rp[rpOff + li], r1 = g_rp[rpOff + li + 1];
    float z = 1.f;
#pragma unroll 4
    for (int j = r0; j < r1; j++) {
        int s = g_col[colOff + j];
        float w = __expf(lrelu(g_als[s * 256 + g] + adi) - es);
        z += w;
        g_ew[(size_t)j * 256 + g] = w;
    }
    float iz = __fdividef(1.f, z);
#pragma unroll 4
    for (int j = r0; j < r1; j++)
        g_ew[(size_t)j * 256 + g] *= iz;
    g_sfa[li * 256 + g] = iz;
}

// ---------------- layers 1,2: fused agg(alphas) + GEMM(W',b') + relu + max-pool ----------------
// lc-major grid (measured best). Threads: fq = t>>5 (f-octet), pair p = t&31.
// Gather loop is pure FMA: alpha read from g_ew, no exp/z/als in the hot loop.
__global__ __launch_bounds__(256) void aggpool_fused_kernel(
    size_t srcOff, size_t dstOff, int rpOff, int colOff, int crpOff, int ccolOff)
{
    __shared__ float sv[2][64 * 66];
    __shared__ float sbb[64];
    int t = threadIdx.x;
    int lc = blockIdx.x >> 2;
    int gb = blockIdx.x & 3;
    int p  = t & 31;
    int fq = t >> 5;
    int gg = gb * 64 + 2 * p;
    int fb = fq * 8;

    if (t < 64) sbb[t] = g_beff[t];

    int m0  = g_rp[crpOff + lc];
    int cnt = g_rp[crpOff + lc + 1] - m0;
    int liA = g_col[ccolOff + m0];
    int liB = (cnt > 1) ? g_col[ccolOff + m0 + 1] : liA;

    float2 izA = *(const float2*)&g_sfa[liA * 256 + gg];
    float2 izB = *(const float2*)&g_sfa[liB * 256 + gg];

    const float* selfA = g_pool + srcOff + ((size_t)liA * 64 + fb) * 256 + gg;
    const float* selfB = g_pool + srcOff + ((size_t)liB * 64 + fb) * 256 + gg;
    float2 accA[8], accB[8];
#pragma unroll
    for (int ff = 0; ff < 8; ff++) {
        float2 sA = *(const float2*)&selfA[(size_t)ff * 256];
        float2 sB = *(const float2*)&selfB[(size_t)ff * 256];
        accA[ff].x = izA.x * sA.x; accA[ff].y = izA.y * sA.y;
        accB[ff].x = izB.x * sB.x; accB[ff].y = izB.y * sB.y;
    }

    int rA0 = g_rp[rpOff + liA], lenA = g_rp[rpOff + liA + 1] - rA0;
    int rB0 = g_rp[rpOff + liB], lenB = g_rp[rpOff + liB + 1] - rB0;
    int len = max(lenA, lenB);

#pragma unroll 4
    for (int j = 0; j < len; j++) {
        if (j < lenA) {
            int s = g_col[colOff + rA0 + j];
            float2 a2 = *(const float2*)&g_ew[(size_t)(rA0 + j) * 256 + gg];
            const float* sr = g_pool + srcOff + ((size_t)s * 64 + fb) * 256 + gg;
#pragma unroll
            for (int ff = 0; ff < 8; ff++) {
                float2 pv = *(const float2*)&sr[(size_t)ff * 256];
                accA[ff].x = fmaf(a2.x, pv.x, accA[ff].x);
                accA[ff].y = fmaf(a2.y, pv.y, accA[ff].y);
            }
        }
        if (j < lenB) {
            int s = g_col[colOff + rB0 + j];
            float2 a2 = *(const float2*)&g_ew[(size_t)(rB0 + j) * 256 + gg];
            const float* sr = g_pool + srcOff + ((size_t)s * 64 + fb) * 256 + gg;
#pragma unroll
            for (int ff = 0; ff < 8; ff++) {
                float2 pv = *(const float2*)&sr[(size_t)ff * 256];
                accB[ff].x = fmaf(a2.x, pv.x, accB[ff].x);
                accB[ff].y = fmaf(a2.y, pv.y, accB[ff].y);
            }
        }
    }

#pragma unroll
    for (int ff = 0; ff < 8; ff++) {
        *(float2*)&sv[0][(fb + ff) * 66 + 2 * p] = accA[ff];
        *(float2*)&sv[1][(fb + ff) * 66 + 2 * p] = accB[ff];
    }
    __syncthreads();

    // GEMM both members: out_f = sum_k v_k * W'[k][f]; W' broadcast-read from global
    float2 oA[8], oB[8];
#pragma unroll
    for (int ff = 0; ff < 8; ff++) { oA[ff] = make_float2(0.f, 0.f); oB[ff] = make_float2(0.f, 0.f); }
#pragma unroll 4
    for (int k = 0; k < 64; k++) {
        float2 vA = *(const float2*)&sv[0][k * 66 + 2 * p];
        float2 vB = *(const float2*)&sv[1][k * 66 + 2 * p];
        float4 w4a = *(const float4*)&g_weff[k * 64 + fb];
        float4 w4b = *(const float4*)&g_weff[k * 64 + fb + 4];
        oA[0].x = fmaf(w4a.x, vA.x, oA[0].x); oA[0].y = fmaf(w4a.x, vA.y, oA[0].y);
        oA[1].x = fmaf(w4a.y, vA.x, oA[1].x); oA[1].y = fmaf(w4a.y, vA.y, oA[1].y);
        oA[2].x = fmaf(w4a.z, vA.x, oA[2].x); oA[2].y = fmaf(w4a.z, vA.y, oA[2].y);
        oA[3].x = fmaf(w4a.w, vA.x, oA[3].x); oA[3].y = fmaf(w4a.w, vA.y, oA[3].y);
        oA[4].x = fmaf(w4b.x, vA.x, oA[4].x); oA[4].y = fmaf(w4b.x, vA.y, oA[4].y);
        oA[5].x = fmaf(w4b.y, vA.x, oA[5].x); oA[5].y = fmaf(w4b.y, vA.y, oA[5].y);
        oA[6].x = fmaf(w4b.z, vA.x, oA[6].x); oA[6].y = fmaf(w4b.z, vA.y, oA[6].y);
        oA[7].x = fmaf(w4b.w, vA.x, oA[7].x); oA[7].y = fmaf(w4b.w, vA.y, oA[7].y);
        oB[0].x = fmaf(w4a.x, vB.x, oB[0].x); oB[0].y = fmaf(w4a.x, vB.y, oB[0].y);
        oB[1].x = fmaf(w4a.y, vB.x, oB[1].x); oB[1].y = fmaf(w4a.y, vB.y, oB[1].y);
        oB[2].x = fmaf(w4a.z, vB.x, oB[2].x); oB[2].y = fmaf(w4a.z, vB.y, oB[2].y);
        oB[3].x = fmaf(w4a.w, vB.x, oB[3].x); oB[3].y = fmaf(w4a.w, vB.y, oB[3].y);
        oB[4].x = fmaf(w4b.x, vB.x, oB[4].x); oB[4].y = fmaf(w4b.x, vB.y, oB[4].y);
        oB[5].x = fmaf(w4b.y, vB.x, oB[5].x); oB[5].y = fmaf(w4b.y, vB.y, oB[5].y);
        oB[6].x = fmaf(w4b.z, vB.x, oB[6].x); oB[6].y = fmaf(w4b.z, vB.y, oB[6].y);
        oB[7].x = fmaf(w4b.w, vB.x, oB[7].x); oB[7].y = fmaf(w4b.w, vB.y, oB[7].y);
    }

    float* dstRow = g_pool + dstOff + ((size_t)lc * 64 + fb) * 256 + gg;
#pragma unroll
    for (int ff = 0; ff < 8; ff++) {
        float bfv = sbb[fb + ff];
        float2 ov;
        ov.x = fmaxf(fmaxf(oA[ff].x + bfv, oB[ff].x + bfv), 0.f);
        ov.y = fmaxf(fmaxf(oA[ff].y + bfv, oB[ff].y + bfv), 0.f);
        *(float2*)&dstRow[(size_t)ff * 256] = ov;
    }
}

// ---------------- BatchNorm statistics (deterministic 2-stage) ----------------
__global__ __launch_bounds__(256) void bn_stats_kernel(size_t poolOff, int ncl) {
    int f  = blockIdx.x >> 2;
    int cq = blockIdx.x & 3;
    int t  = threadIdx.x;
    int cQ = ncl >> 2;
    float s = 0.f, ss = 0.f;
    for (int c = cq * cQ; c < (cq + 1) * cQ; c++) {
        float v = g_pool[poolOff + ((size_t)c * 64 + f) * 256 + t];
        s += v;
        ss = fmaf(v, v, ss);
    }
    __shared__ float shS[256], shQ[256];
    shS[t] = s; shQ[t] = ss;
    __syncthreads();
    for (int o = 128; o; o >>= 1) {
        if (t < o) { shS[t] += shS[t + o]; shQ[t] += shQ[t + o]; }
        __syncthreads();
    }
    if (t == 0) {
        g_partS[f * 4 + cq]  = shS[0];
        g_partSS[f * 4 + cq] = shQ[0];
    }
}

__global__ void bn_final_kernel(int nrows) {
    int f = threadIdx.x;   // 64 threads
    double S = 0.0, SS = 0.0;
    for (int q = 0; q < 4; q++) {
        S  += (double)g_partS[f * 4 + q];
        SS += (double)g_partSS[f * 4 + q];
    }
    double mu  = S / nrows;
    double var = SS / nrows - mu * mu;
    g_mean[f] = (float)mu;
    g_rstd[f] = (float)rsqrt(var + 1e-5);
}

// ---------------- finalize: BN + transpose [c][f][g] -> out[g][c*64+f] ----------------
__global__ __launch_bounds__(256) void finalize_kernel(float* __restrict__ out) {
    __shared__ float sm[64 * 65];
    int c  = blockIdx.x >> 2;
    int gb = blockIdx.x & 3;
    int t  = threadIdx.x;
    int g  = t & 63;
    int fq = t >> 6;
#pragma unroll
    for (int ff = 0; ff < 16; ff++) {
        int f = fq * 16 + ff;
        float v = g_pool[((size_t)c * 64 + f) * 256 + gb * 64 + g];
        sm[f * 65 + g] = (v - g_mean[f]) * g_rstd[f];
    }
    __syncthreads();
#pragma unroll
    for (int gg = 0; gg < 16; gg++) {
        int g2 = fq * 16 + gg;
        int f2 = t & 63;
        out[(size_t)(gb * 64 + g2) * (NS3 * 64) + c * 64 + f2] = sm[f2 * 65 + g2];
    }
}

// ---------------- host driver ----------------
extern "C" void kernel_launch(void* const* d_in, const int* in_sizes, int n_in,
                              void* d_out, int out_size)
{
    (void)n_in; (void)out_size;
    const float* x = (const float*)d_in[0];
    const float *W[3], *As[3], *Ad[3], *Bi[3];
    const int *E[3], *C[3];

    bool dictOrder = (in_sizes[5] == 2 * E0);
    if (dictOrder) {
        int p = 1;
        for (int l = 0; l < 3; l++) {
            W[l]  = (const float*)d_in[p + 0];
            As[l] = (const float*)d_in[p + 1];
            Ad[l] = (const float*)d_in[p + 2];
            Bi[l] = (const float*)d_in[p + 3];
            E[l]  = (const int*)d_in[p + 4];
            C[l]  = (const int*)d_in[p + 5];
            p += 6;
        }
    } else {
        for (int l = 0; l < 3; l++) {
            W[l]  = (const float*)d_in[1 + 4 * l];
            As[l] = (const float*)d_in[2 + 4 * l];
            Ad[l] = (const float*)d_in[3 + 4 * l];
            Bi[l] = (const float*)d_in[4 + 4 * l];
        }
        E[0] = (const int*)d_in[13]; E[1] = (const int*)d_in[14]; E[2] = (const int*)d_in[15];
        C[0] = (const int*)d_in[16]; C[1] = (const int*)d_in[17]; C[2] = (const int*)d_in[18];
    }

    // ---- CSR build: edge lists + cluster membership (shared across batch) ----
    zero_deg_kernel<<<(DEG_TOT + 255) / 256, 256>>>();
    count_all_kernel<<<252, 256>>>(E[0], E[1], E[2], C[0], C[1], C[2]);
    scan_all_kernel<<<6, 1024>>>();
    scatter_all_kernel<<<252, 256>>>(E[0], E[1], E[2], C[0], C[1], C[2]);

    // ---- layer 0 (no BN on input) ----
    prep0_kernel<<<1, 64>>>(W[0], As[0], Ad[0]);
    trans_att0_kernel<<<(NS0 / 8) * 2, 256>>>(x);
    agg0_fused_kernel<<<NS1 * 2, 256>>>(W[0], Bi[0]);
    bn_stats_kernel<<<256, 256>>>(0, NS1);

    // ---- layer 1: pool A (off 0) -> pool B ----
    bn_prep_kernel<<<1, 256>>>(W[1], As[1], Ad[1], Bi[1], NS1 * BB);
    att_kernel<<<NS1, 256>>>(0);
    ew_kernel<<<NS1, 256>>>(RP1, COL1);
    aggpool_fused_kernel<<<NS2 * 4, 256>>>(0, POOLB_OFF, RP1, COL1, CRP1, CCOL1);
    bn_stats_kernel<<<256, 256>>>(POOLB_OFF, NS2);

    // ---- layer 2: pool B -> pool A (off 0) ----
    bn_prep_kernel<<<1, 256>>>(W[2], As[2], Ad[2], Bi[2], NS2 * BB);
    att_kernel<<<NS2, 256>>>(POOLB_OFF);
    ew_kernel<<<NS2, 256>>>(RP2, COL2);
    aggpool_fused_kernel<<<NS3 * 4, 256>>>(POOLB_OFF, 0, RP2, COL2, CRP2, CCOL2);
    bn_stats_kernel<<<256, 256>>>(0, NS3);

    // ---- final BN + output ----
    bn_final_kernel<<<1, 64>>>(NS3 * BB);
    finalize_kernel<<<NS3 * 4, 256>>>((float*)d_out);
}

// round 17
// speedup vs baseline: 1.1606x; 1.1606x over previous
#include <cuda_runtime.h>
#include <cstddef>

#define BB  256
#define NS0 4096
#define NS1 2048
#define NS2 1024
#define NS3 512
#define E0  32768
#define E1  16384
#define E2  8192
#define DD  64

// ---- deg array layout: edge degs then cluster degs ----
#define EDEG0 0
#define EDEG1 (NS0)
#define EDEG2 (NS0 + NS1)
#define CDEG0 (NS0 + NS1 + NS2)
#define CDEG1 (CDEG0 + NS1)
#define CDEG2 (CDEG1 + NS2)
#define DEG_TOT (CDEG2 + NS3)

// ---- rp array layout ----
#define RP0 0
#define RP1 (NS0 + 1)
#define RP2 (NS0 + NS1 + 2)
#define CRP0 (NS0 + NS1 + NS2 + 3)
#define CRP1 (CRP0 + NS1 + 1)
#define CRP2 (CRP1 + NS2 + 1)
#define RP_TOT (CRP2 + NS3 + 1)

// ---- col array layout ----
#define COL0 0
#define COL1 (E0)
#define COL2 (E0 + E1)
#define CCOL0 (E0 + E1 + E2)
#define CCOL1 (CCOL0 + NS0)
#define CCOL2 (CCOL1 + NS1)
#define COL_TOT (CCOL2 + NS2)

// pool ping-pong: region A at 0 (max NS1 clusters), region B after it
#define POOLB_OFF ((size_t)NS1 * DD * BB)

// ---------------- scratch (device globals; no allocation) ----------------
__device__ float g_pool[(size_t)(NS1 + NS2) * DD * BB];  // 201 MB, [c][f][g] fp32
__device__ float g_x[(size_t)NS0 * 3 * BB];              // layer-0 x, [li][k][g]
__device__ float g_als[NS0 * BB];                        // [li][g]
__device__ float g_ald[NS0 * BB];
__device__ int   g_deg[DEG_TOT];
__device__ int   g_rp[RP_TOT];
__device__ int   g_wp[RP_TOT];
__device__ int   g_col[COL_TOT];
__device__ float g_partS[64 * 4];
__device__ float g_partSS[64 * 4];
__device__ float g_mean[DD];
__device__ float g_rstd[DD];
__device__ float g_qas[DD];
__device__ float g_qad[DD];
__device__ float g_cas;
__device__ float g_cad;
__device__ float g_weff[DD * DD];      // rstd-folded weights (layers 1,2)
__device__ float g_beff[DD];           // mean/rstd-folded bias

__device__ __forceinline__ float lrelu(float x) { return x > 0.f ? x : 0.2f * x; }

// ---------------- CSR build (edges AND cluster membership) ----------------
__global__ void zero_deg_kernel() {
    int i = blockIdx.x * blockDim.x + threadIdx.x;
    if (i < DEG_TOT) g_deg[i] = 0;
}

__global__ void count_all_kernel(const int* __restrict__ e0d, const int* __restrict__ e1d,
                                 const int* __restrict__ e2d, const int* __restrict__ c0d,
                                 const int* __restrict__ c1d, const int* __restrict__ c2d) {
    int b = blockIdx.x;
    int tid = threadIdx.x;
    if (b < 224) {
        const int* e; int epb, off, j0;
        if (b < 128)      { e = e0d; epb = E0; off = EDEG0; j0 = b * 256; }
        else if (b < 192) { e = e1d; epb = E1; off = EDEG1; j0 = (b - 128) * 256; }
        else              { e = e2d; epb = E2; off = EDEG2; j0 = (b - 192) * 256; }
        int j = j0 + tid;
        if (j < epb) atomicAdd(&g_deg[off + e[epb + j]], 1);
    } else {
        const int* c; int n, off, j0;
        if (b < 240)      { c = c0d; n = NS0; off = CDEG0; j0 = (b - 224) * 256; }
        else if (b < 248) { c = c1d; n = NS1; off = CDEG1; j0 = (b - 240) * 256; }
        else              { c = c2d; n = NS2; off = CDEG2; j0 = (b - 248) * 256; }
        int j = j0 + tid;
        if (j < n) atomicAdd(&g_deg[off + c[j]], 1);
    }
}

__global__ void scan_all_kernel() {
    const int degOffT[6] = {EDEG0, EDEG1, EDEG2, CDEG0, CDEG1, CDEG2};
    const int rpOffT[6]  = {RP0, RP1, RP2, CRP0, CRP1, CRP2};
    const int nT[6]      = {NS0, NS1, NS2, NS1, NS2, NS3};
    int degOff = degOffT[blockIdx.x], rpOff = rpOffT[blockIdx.x], n = nT[blockIdx.x];

    __shared__ int tsum[1024];
    int t = threadIdx.x;
    int chunk = (n + 1023) >> 10;
    int start = t * chunk;
    int s = 0;
    for (int i = 0; i < chunk; i++) {
        int idx = start + i;
        if (idx < n) s += g_deg[degOff + idx];
    }
    tsum[t] = s;
    __syncthreads();
    for (int off = 1; off < 1024; off <<= 1) {
        int v = (t >= off) ? tsum[t - off] : 0;
        __syncthreads();
        tsum[t] += v;
        __syncthreads();
    }
    int run = (t == 0) ? 0 : tsum[t - 1];
    for (int i = 0; i < chunk; i++) {
        int idx = start + i;
        if (idx < n) {
            g_rp[rpOff + idx] = run;
            g_wp[rpOff + idx] = run;
            run += g_deg[degOff + idx];
        }
    }
    if (t == 1023) g_rp[rpOff + n] = tsum[1023];
}

__global__ void scatter_all_kernel(const int* __restrict__ e0d, const int* __restrict__ e1d,
                                   const int* __restrict__ e2d, const int* __restrict__ c0d,
                                   const int* __restrict__ c1d, const int* __restrict__ c2d) {
    int b = blockIdx.x;
    int tid = threadIdx.x;
    if (b < 224) {
        const int* e; int epb, rpOff, colOff, j0;
        if (b < 128)      { e = e0d; epb = E0; rpOff = RP0; colOff = COL0; j0 = b * 256; }
        else if (b < 192) { e = e1d; epb = E1; rpOff = RP1; colOff = COL1; j0 = (b - 128) * 256; }
        else              { e = e2d; epb = E2; rpOff = RP2; colOff = COL2; j0 = (b - 192) * 256; }
        int j = j0 + tid;
        if (j < epb) {
            int s = e[j];
            int d = e[epb + j];
            int p = atomicAdd(&g_wp[rpOff + d], 1);
            g_col[colOff + p] = s;
        }
    } else {
        const int* c; int n, rpOff, colOff, j0;
        if (b < 240)      { c = c0d; n = NS0; rpOff = CRP0; colOff = CCOL0; j0 = (b - 224) * 256; }
        else if (b < 248) { c = c1d; n = NS1; rpOff = CRP1; colOff = CCOL1; j0 = (b - 240) * 256; }
        else              { c = c2d; n = NS2; rpOff = CRP2; colOff = CCOL2; j0 = (b - 248) * 256; }
        int j = j0 + tid;
        if (j < n) {
            int p = atomicAdd(&g_wp[rpOff + c[j]], 1);
            g_col[colOff + p] = j;
        }
    }
}

// ---------------- layer-0 prep: qas = W@a (no BN) ----------------
__global__ void prep0_kernel(const float* __restrict__ Wg,
                             const float* __restrict__ as_, const float* __restrict__ ad_) {
    int t = threadIdx.x;   // 64
    if (t < 3) {
        float ps = 0.f, pd = 0.f;
        for (int f = 0; f < 64; f++) {
            float w = Wg[t * 64 + f];
            ps = fmaf(w, as_[f], ps);
            pd = fmaf(w, ad_[f], pd);
        }
        g_qas[t] = ps;
        g_qad[t] = pd;
    }
    if (t == 0) { g_cas = 0.f; g_cad = 0.f; }
}

// ---------------- layers 1,2: BN finalize + fold into W', b', qas, cas ----------------
__global__ void bn_prep_kernel(const float* __restrict__ Wg, const float* __restrict__ as_,
                               const float* __restrict__ ad_, const float* __restrict__ bias,
                               int nrows) {
    __shared__ float smean[64], srstd[64], sc[64], sd[64];
    int t = threadIdx.x;
    if (t < 64) {
        double S  = (double)g_partS[t * 4] + g_partS[t * 4 + 1] + g_partS[t * 4 + 2] + g_partS[t * 4 + 3];
        double SS = (double)g_partSS[t * 4] + g_partSS[t * 4 + 1] + g_partSS[t * 4 + 2] + g_partSS[t * 4 + 3];
        double mu  = S / nrows;
        double var = SS / nrows - mu * mu;
        float m = (float)mu;
        float r = (float)rsqrt(var + 1e-5);
        smean[t] = m; srstd[t] = r;
        g_mean[t] = m; g_rstd[t] = r;
    }
    __syncthreads();
    if (t < 64) {
        float ps = 0.f, pd = 0.f;
        for (int f = 0; f < 64; f++) {
            float w = Wg[t * 64 + f];
            ps = fmaf(w, as_[f], ps);
            pd = fmaf(w, ad_[f], pd);
        }
        ps *= srstd[t]; pd *= srstd[t];
        g_qas[t] = ps; g_qad[t] = pd;
        sc[t] = smean[t] * ps; sd[t] = smean[t] * pd;
    }
    for (int i = t; i < 4096; i += 256)
        g_weff[i] = srstd[i >> 6] * Wg[i];
    __syncthreads();
    if (t < 64) {
        float bb = bias[t];
        for (int k = 0; k < 64; k++)
            bb -= srstd[k] * smean[k] * Wg[k * 64 + t];
        g_beff[t] = bb;
    }
    if (t == 0) {
        float S = 0.f;
        for (int k = 0; k < 64; k++) S += sc[k];
        g_cas = S;
    }
    if (t == 1) {
        float D = 0.f;
        for (int k = 0; k < 64; k++) D += sd[k];
        g_cad = D;
    }
}

// ---------------- layer 0: transpose x to graph-innermost + attention logits ----------------
__global__ __launch_bounds__(256) void trans_att0_kernel(const float* __restrict__ xin) {
    __shared__ float sm[24 * 132];
    __shared__ float qs[3], qd[3];
    int t = threadIdx.x;
    int li0 = (blockIdx.x >> 1) * 8;
    int g0  = (blockIdx.x & 1) * 128;
    if (t < 3) { qs[t] = g_qas[t]; qd[t] = g_qad[t]; }

    for (int i = t; i < 3072; i += 256) {
        int g = i / 24;
        int rem = i - g * 24;           // li*3 + k
        sm[rem * 132 + g] = xin[((size_t)(g0 + g) * NS0 + li0 + rem / 3) * 3 + rem % 3];
    }
    __syncthreads();
    for (int i = t; i < 3072; i += 256) {
        int r = i >> 7;                  // 0..23
        int g = i & 127;
        g_x[((size_t)(li0 + r / 3) * 3 + r % 3) * 256 + g0 + g] = sm[r * 132 + g];
    }
    for (int i = t; i < 1024; i += 256) {
        int li = i >> 7;
        int g  = i & 127;
        const float* row = sm + li * 3 * 132 + g;
        float a = row[0] * qs[0] + row[132] * qs[1] + row[264] * qs[2];
        float d = row[0] * qd[0] + row[132] * qd[1] + row[264] * qd[2];
        g_als[(li0 + li) * 256 + g0 + g] = a;
        g_ald[(li0 + li) * 256 + g0 + g] = d;
    }
}

// ---------------- layer 0: fused x-space agg + GEMM(K=3) + bias + relu + max-pool ----------------
__global__ __launch_bounds__(256) void agg0_fused_kernel(const float* __restrict__ Wg,
                                                         const float* __restrict__ bias) {
    __shared__ float sw[192], sb[64];
    __shared__ float su[2 * 396];       // [m][k*132 + g]
    int t = threadIdx.x;
    int lc = blockIdx.x >> 1;
    int gb = blockIdx.x & 1;
    int m  = t >> 7;
    int g  = t & 127;
    int gg = gb * 128 + g;

    if (t < 192) sw[t] = Wg[t];
    else sb[t - 192] = bias[t - 192];

    int m0  = g_rp[CRP0 + lc];
    int cnt = g_rp[CRP0 + lc + 1] - m0;
    int li  = g_col[CCOL0 + m0 + (m < cnt ? m : 0)];

    float adi = g_ald[li * 256 + gg];
    float es  = lrelu(g_als[li * 256 + gg] + adi);
    float z = 1.f;
    float u0 = g_x[((size_t)li * 3 + 0) * 256 + gg];
    float u1 = g_x[((size_t)li * 3 + 1) * 256 + gg];
    float u2 = g_x[((size_t)li * 3 + 2) * 256 + gg];

    int r0 = g_rp[RP0 + li], r1 = g_rp[RP0 + li + 1];
#pragma unroll 4
    for (int j = r0; j < r1; j++) {
        int s = g_col[COL0 + j];
        float w = __expf(lrelu(g_als[s * 256 + gg] + adi) - es);
        z += w;
        u0 = fmaf(w, g_x[((size_t)s * 3 + 0) * 256 + gg], u0);
        u1 = fmaf(w, g_x[((size_t)s * 3 + 1) * 256 + gg], u1);
        u2 = fmaf(w, g_x[((size_t)s * 3 + 2) * 256 + gg], u2);
    }
    float iz = __fdividef(1.f, z);
    su[m * 396 + 0   + g] = u0 * iz;
    su[m * 396 + 132 + g] = u1 * iz;
    su[m * 396 + 264 + g] = u2 * iz;
    __syncthreads();

    int mh = t >> 7;
    float a0 = su[0   + g], a1 = su[132 + g], a2 = su[264 + g];
    float b0 = su[396 + g], b1 = su[528 + g], b2 = su[660 + g];
    size_t outBase = ((size_t)lc * 64 + mh * 32) * 256 + gb * 128 + g;
#pragma unroll 8
    for (int ff = 0; ff < 32; ff++) {
        int f = mh * 32 + ff;
        float w0 = sw[f], w1 = sw[64 + f], w2 = sw[128 + f];
        float oA = sb[f] + a0 * w0 + a1 * w1 + a2 * w2;
        float oB = sb[f] + b0 * w0 + b1 * w1 + b2 * w2;
        g_pool[outBase + (size_t)ff * 256] = fmaxf(fmaxf(oA, oB), 0.f);
    }
}

// ---------------- layers 1,2: attention logits from raw pool (BN folded into q) ----------------
__global__ __launch_bounds__(256) void att_kernel(size_t poolOff) {
    __shared__ float qs[64], qd[64];
    __shared__ float sredS[2048], sredD[2048];
    int t = threadIdx.x;
    int tc = t >> 5, tr = t & 31;
    int li = blockIdx.x;
    if (t < 64) { qs[t] = g_qas[t]; qd[t] = g_qad[t]; }
    __syncthreads();

    const float* row = g_pool + poolOff + (size_t)li * 64 * 256;
    float ps[8], pd[8];
#pragma unroll
    for (int i = 0; i < 8; i++) { ps[i] = 0.f; pd[i] = 0.f; }
#pragma unroll
    for (int j = 0; j < 8; j++) {
        int f = tc * 8 + j;
        float qv = qs[f], qw = qd[f];
#pragma unroll
        for (int i = 0; i < 8; i++) {
            float v = row[(size_t)f * 256 + tr + 32 * i];
            ps[i] = fmaf(v, qv, ps[i]);
            pd[i] = fmaf(v, qw, pd[i]);
        }
    }
#pragma unroll
    for (int i = 0; i < 8; i++) {
        sredS[(tc * 8 + i) * 32 + tr] = ps[i];
        sredD[(tc * 8 + i) * 32 + tr] = pd[i];
    }
    __syncthreads();
    {
        int i = t >> 5, r = t & 31;
        float S = 0.f, D = 0.f;
#pragma unroll
        for (int c = 0; c < 8; c++) {
            S += sredS[(c * 8 + i) * 32 + r];
            D += sredD[(c * 8 + i) * 32 + r];
        }
        g_als[li * 256 + r + 32 * i] = S - g_cas;
        g_ald[li * 256 + r + 32 * i] = D - g_cad;
    }
}

// ---------------- layers 1,2: fused agg(both members) + GEMM(W',b') + relu + max-pool ----------------
// GB-MAJOR grid: gb = bid >> clshift, lc = bid & (ncl-1) — one 33MB source slice
// in flight at a time so the ~9x gather reuse stays L2-resident.
__global__ __launch_bounds__(256) void aggpool_fused_kernel(
    size_t srcOff, size_t dstOff, int rpOff, int colOff, int crpOff, int ccolOff, int clshift)
{
    __shared__ float sv[2][64 * 66];
    __shared__ float sbb[64];
    int t = threadIdx.x;
    int lc = blockIdx.x & ((1 << clshift) - 1);
    int gb = blockIdx.x >> clshift;
    int p  = t & 31;
    int fq = t >> 5;
    int gg = gb * 64 + 2 * p;
    int fb = fq * 8;

    if (t < 64) sbb[t] = g_beff[t];

    int m0  = g_rp[crpOff + lc];
    int cnt = g_rp[crpOff + lc + 1] - m0;
    int liA = g_col[ccolOff + m0];
    int liB = (cnt > 1) ? g_col[ccolOff + m0 + 1] : liA;

    float2 adA = *(const float2*)&g_ald[liA * 256 + gg];
    float2 asA = *(const float2*)&g_als[liA * 256 + gg];
    float2 adB = *(const float2*)&g_ald[liB * 256 + gg];
    float2 asB = *(const float2*)&g_als[liB * 256 + gg];
    float esA0 = lrelu(asA.x + adA.x), esA1 = lrelu(asA.y + adA.y);
    float esB0 = lrelu(asB.x + adB.x), esB1 = lrelu(asB.y + adB.y);
    float zA0 = 1.f, zA1 = 1.f, zB0 = 1.f, zB1 = 1.f;

    const float* selfA = g_pool + srcOff + ((size_t)liA * 64 + fb) * 256 + gg;
    const float* selfB = g_pool + srcOff + ((size_t)liB * 64 + fb) * 256 + gg;
    float2 accA[8], accB[8];
#pragma unroll
    for (int ff = 0; ff < 8; ff++) {
        accA[ff] = *(const float2*)&selfA[(size_t)ff * 256];
        accB[ff] = *(const float2*)&selfB[(size_t)ff * 256];
    }

    int rA0 = g_rp[rpOff + liA], lenA = g_rp[rpOff + liA + 1] - rA0;
    int rB0 = g_rp[rpOff + liB], lenB = g_rp[rpOff + liB + 1] - rB0;
    int len = max(lenA, lenB);

#pragma unroll 4
    for (int j = 0; j < len; j++) {
        if (j < lenA) {
            int s = g_col[colOff + rA0 + j];
            float2 al = *(const float2*)&g_als[s * 256 + gg];
            float w0 = __expf(lrelu(al.x + adA.x) - esA0);
            float w1 = __expf(lrelu(al.y + adA.y) - esA1);
            zA0 += w0; zA1 += w1;
            const float* sr = g_pool + srcOff + ((size_t)s * 64 + fb) * 256 + gg;
#pragma unroll
            for (int ff = 0; ff < 8; ff++) {
                float2 pv = *(const float2*)&sr[(size_t)ff * 256];
                accA[ff].x = fmaf(w0, pv.x, accA[ff].x);
                accA[ff].y = fmaf(w1, pv.y, accA[ff].y);
            }
        }
        if (j < lenB) {
            int s = g_col[colOff + rB0 + j];
            float2 al = *(const float2*)&g_als[s * 256 + gg];
            float w0 = __expf(lrelu(al.x + adB.x) - esB0);
            float w1 = __expf(lrelu(al.y + adB.y) - esB1);
            zB0 += w0; zB1 += w1;
            const float* sr = g_pool + srcOff + ((size_t)s * 64 + fb) * 256 + gg;
#pragma unroll
            for (int ff = 0; ff < 8; ff++) {
                float2 pv = *(const float2*)&sr[(size_t)ff * 256];
                accB[ff].x = fmaf(w0, pv.x, accB[ff].x);
                accB[ff].y = fmaf(w1, pv.y, accB[ff].y);
            }
        }
    }

    float iA0 = __fdividef(1.f, zA0), iA1 = __fdividef(1.f, zA1);
    float iB0 = __fdividef(1.f, zB0), iB1 = __fdividef(1.f, zB1);
#pragma unroll
    for (int ff = 0; ff < 8; ff++) {
        float2 vA, vB;
        vA.x = accA[ff].x * iA0; vA.y = accA[ff].y * iA1;
        vB.x = accB[ff].x * iB0; vB.y = accB[ff].y * iB1;
        *(float2*)&sv[0][(fb + ff) * 66 + 2 * p] = vA;
        *(float2*)&sv[1][(fb + ff) * 66 + 2 * p] = vB;
    }
    __syncthreads();

    // GEMM both members: out_f = sum_k v_k * W'[k][f]; W' broadcast-read from global
    float2 oA[8], oB[8];
#pragma unroll
    for (int ff = 0; ff < 8; ff++) { oA[ff] = make_float2(0.f, 0.f); oB[ff] = make_float2(0.f, 0.f); }
#pragma unroll 4
    for (int k = 0; k < 64; k++) {
        float2 vA = *(const float2*)&sv[0][k * 66 + 2 * p];
        float2 vB = *(const float2*)&sv[1][k * 66 + 2 * p];
        float4 w4a = *(const float4*)&g_weff[k * 64 + fb];
        float4 w4b = *(const float4*)&g_weff[k * 64 + fb + 4];
        oA[0].x = fmaf(w4a.x, vA.x, oA[0].x); oA[0].y = fmaf(w4a.x, vA.y, oA[0].y);
        oA[1].x = fmaf(w4a.y, vA.x, oA[1].x); oA[1].y = fmaf(w4a.y, vA.y, oA[1].y);
        oA[2].x = fmaf(w4a.z, vA.x, oA[2].x); oA[2].y = fmaf(w4a.z, vA.y, oA[2].y);
        oA[3].x = fmaf(w4a.w, vA.x, oA[3].x); oA[3].y = fmaf(w4a.w, vA.y, oA[3].y);
        oA[4].x = fmaf(w4b.x, vA.x, oA[4].x); oA[4].y = fmaf(w4b.x, vA.y, oA[4].y);
        oA[5].x = fmaf(w4b.y, vA.x, oA[5].x); oA[5].y = fmaf(w4b.y, vA.y, oA[5].y);
        oA[6].x = fmaf(w4b.z, vA.x, oA[6].x); oA[6].y = fmaf(w4b.z, vA.y, oA[6].y);
        oA[7].x = fmaf(w4b.w, vA.x, oA[7].x); oA[7].y = fmaf(w4b.w, vA.y, oA[7].y);
        oB[0].x = fmaf(w4a.x, vB.x, oB[0].x); oB[0].y = fmaf(w4a.x, vB.y, oB[0].y);
        oB[1].x = fmaf(w4a.y, vB.x, oB[1].x); oB[1].y = fmaf(w4a.y, vB.y, oB[1].y);
        oB[2].x = fmaf(w4a.z, vB.x, oB[2].x); oB[2].y = fmaf(w4a.z, vB.y, oB[2].y);
        oB[3].x = fmaf(w4a.w, vB.x, oB[3].x); oB[3].y = fmaf(w4a.w, vB.y, oB[3].y);
        oB[4].x = fmaf(w4b.x, vB.x, oB[4].x); oB[4].y = fmaf(w4b.x, vB.y, oB[4].y);
        oB[5].x = fmaf(w4b.y, vB.x, oB[5].x); oB[5].y = fmaf(w4b.y, vB.y, oB[5].y);
        oB[6].x = fmaf(w4b.z, vB.x, oB[6].x); oB[6].y = fmaf(w4b.z, vB.y, oB[6].y);
        oB[7].x = fmaf(w4b.w, vB.x, oB[7].x); oB[7].y = fmaf(w4b.w, vB.y, oB[7].y);
    }

    float* dstRow = g_pool + dstOff + ((size_t)lc * 64 + fb) * 256 + gg;
#pragma unroll
    for (int ff = 0; ff < 8; ff++) {
        float bfv = sbb[fb + ff];
        float2 ov;
        ov.x = fmaxf(fmaxf(oA[ff].x + bfv, oB[ff].x + bfv), 0.f);
        ov.y = fmaxf(fmaxf(oA[ff].y + bfv, oB[ff].y + bfv), 0.f);
        *(float2*)&dstRow[(size_t)ff * 256] = ov;
    }
}

// ---------------- BatchNorm statistics (deterministic 2-stage) ----------------
__global__ __launch_bounds__(256) void bn_stats_kernel(size_t poolOff, int ncl) {
    int f  = blockIdx.x >> 2;
    int cq = blockIdx.x & 3;
    int t  = threadIdx.x;
    int cQ = ncl >> 2;
    float s = 0.f, ss = 0.f;
    for (int c = cq * cQ; c < (cq + 1) * cQ; c++) {
        float v = g_pool[poolOff + ((size_t)c * 64 + f) * 256 + t];
        s += v;
        ss = fmaf(v, v, ss);
    }
    __shared__ float shS[256], shQ[256];
    shS[t] = s; shQ[t] = ss;
    __syncthreads();
    for (int o = 128; o; o >>= 1) {
        if (t < o) { shS[t] += shS[t + o]; shQ[t] += shQ[t + o]; }
        __syncthreads();
    }
    if (t == 0) {
        g_partS[f * 4 + cq]  = shS[0];
        g_partSS[f * 4 + cq] = shQ[0];
    }
}

__global__ void bn_final_kernel(int nrows) {
    int f = threadIdx.x;   // 64 threads
    double S = 0.0, SS = 0.0;
    for (int q = 0; q < 4; q++) {
        S  += (double)g_partS[f * 4 + q];
        SS += (double)g_partSS[f * 4 + q];
    }
    double mu  = S / nrows;
    double var = SS / nrows - mu * mu;
    g_mean[f] = (float)mu;
    g_rstd[f] = (float)rsqrt(var + 1e-5);
}

// ---------------- finalize: BN + transpose [c][f][g] -> out[g][c*64+f] ----------------
__global__ __launch_bounds__(256) void finalize_kernel(float* __restrict__ out) {
    __shared__ float sm[64 * 65];
    int c  = blockIdx.x >> 2;
    int gb = blockIdx.x & 3;
    int t  = threadIdx.x;
    int g  = t & 63;
    int fq = t >> 6;
#pragma unroll
    for (int ff = 0; ff < 16; ff++) {
        int f = fq * 16 + ff;
        float v = g_pool[((size_t)c * 64 + f) * 256 + gb * 64 + g];
        sm[f * 65 + g] = (v - g_mean[f]) * g_rstd[f];
    }
    __syncthreads();
#pragma unroll
    for (int gg = 0; gg < 16; gg++) {
        int g2 = fq * 16 + gg;
        int f2 = t & 63;
        out[(size_t)(gb * 64 + g2) * (NS3 * 64) + c * 64 + f2] = sm[f2 * 65 + g2];
    }
}

// ---------------- host driver ----------------
extern "C" void kernel_launch(void* const* d_in, const int* in_sizes, int n_in,
                              void* d_out, int out_size)
{
    (void)n_in; (void)out_size;
    const float* x = (const float*)d_in[0];
    const float *W[3], *As[3], *Ad[3], *Bi[3];
    const int *E[3], *C[3];

    bool dictOrder = (in_sizes[5] == 2 * E0);
    if (dictOrder) {
        int p = 1;
        for (int l = 0; l < 3; l++) {
            W[l]  = (const float*)d_in[p + 0];
            As[l] = (const float*)d_in[p + 1];
            Ad[l] = (const float*)d_in[p + 2];
            Bi[l] = (const float*)d_in[p + 3];
            E[l]  = (const int*)d_in[p + 4];
            C[l]  = (const int*)d_in[p + 5];
            p += 6;
        }
    } else {
        for (int l = 0; l < 3; l++) {
            W[l]  = (const float*)d_in[1 + 4 * l];
            As[l] = (const float*)d_in[2 + 4 * l];
            Ad[l] = (const float*)d_in[3 + 4 * l];
            Bi[l] = (const float*)d_in[4 + 4 * l];
        }
        E[0] = (const int*)d_in[13]; E[1] = (const int*)d_in[14]; E[2] = (const int*)d_in[15];
        C[0] = (const int*)d_in[16]; C[1] = (const int*)d_in[17]; C[2] = (const int*)d_in[18];
    }

    // ---- CSR build: edge lists + cluster membership (shared across batch) ----
    zero_deg_kernel<<<(DEG_TOT + 255) / 256, 256>>>();
    count_all_kernel<<<252, 256>>>(E[0], E[1], E[2], C[0], C[1], C[2]);
    scan_all_kernel<<<6, 1024>>>();
    scatter_all_kernel<<<252, 256>>>(E[0], E[1], E[2], C[0], C[1], C[2]);

    // ---- layer 0 (no BN on input) ----
    prep0_kernel<<<1, 64>>>(W[0], As[0], Ad[0]);
    trans_att0_kernel<<<(NS0 / 8) * 2, 256>>>(x);
    agg0_fused_kernel<<<NS1 * 2, 256>>>(W[0], Bi[0]);
    bn_stats_kernel<<<256, 256>>>(0, NS1);

    // ---- layer 1: pool A (off 0) -> pool B ----
    bn_prep_kernel<<<1, 256>>>(W[1], As[1], Ad[1], Bi[1], NS1 * BB);
    att_kernel<<<NS1, 256>>>(0);
    aggpool_fused_kernel<<<NS2 * 4, 256>>>(0, POOLB_OFF, RP1, COL1, CRP1, CCOL1, 10);
    bn_stats_kernel<<<256, 256>>>(POOLB_OFF, NS2);

    // ---- layer 2: pool B -> pool A (off 0) ----
    bn_prep_kernel<<<1, 256>>>(W[2], As[2], Ad[2], Bi[2], NS2 * BB);
    att_kernel<<<NS2, 256>>>(POOLB_OFF);
    aggpool_fused_kernel<<<NS3 * 4, 256>>>(POOLB_OFF, 0, RP2, COL2, CRP2, CCOL2, 9);
    bn_stats_kernel<<<256, 256>>>(0, NS3);

    // ---- final BN + output ----
    bn_final_kernel<<<1, 64>>>(NS3 * BB);
    finalize_kernel<<<NS3 * 4, 256>>>((float*)d_out);
}